// round 1
// baseline (speedup 1.0000x reference)
#include <cuda_runtime.h>
#include <cuda_bf16.h>

// QuantumConv2D analytical collapse:
//   out[b,c,h,w] = cos(theta[9]) * prod_{3x3 patch} cos(x[b,c,h+i,w+j])
//
// Derivation (Heisenberg picture on Z_last):
//   - RY(theta_q) for q != 9 commute with Z_9 and cancel.
//   - RY(t9)^† Z RY(t9) = cos(t9) Z - sin(t9) X
//   - CNOT chain pulls Z_9 back to Z_0...Z_9 ; X_9 is invariant.
//   - Product state: <Z_q> = cos(a_q), <X_9> = sin(0) = 0, ancilla Z factor = cos(0)=1.
// => <Z_last> = cos(theta[9]) * prod_{q=0..8} cos(pixel_q)

#define IMG_H 64
#define IMG_W 64
#define OUT_H 62
#define OUT_W 62
#define TILE_H 16          // output rows per block
#define SMEM_W 65          // padded row width (kills bank conflicts)

__global__ __launch_bounds__(256)
void qconv3x3_coscos_kernel(const float* __restrict__ x,
                            const float* __restrict__ theta,
                            float* __restrict__ out)
{
    const int bc = blockIdx.x;              // (b*C + c) in [0, 48)
    const int r0 = blockIdx.y * TILE_H;     // first output row of this band

    __shared__ float sc[(TILE_H + 2) * SMEM_W];

    const float* img = x + bc * (IMG_H * IMG_W);
    const int tid = threadIdx.x;

    // Input rows needed: r0 .. r0 + TILE_H + 1 (clamped to image)
    const int nrows = min(TILE_H + 2, IMG_H - r0);

    // Load band, computing cos ONCE per input pixel.
    for (int i = tid; i < nrows * IMG_W; i += blockDim.x) {
        const int r = i >> 6;         // /64
        const int c = i & 63;         // %64
        sc[r * SMEM_W + c] = cosf(img[(r0 + r) * IMG_W + c]);
    }
    __syncthreads();

    const float cT = cosf(__ldg(&theta[9]));

    const int out_rows = min(TILE_H, OUT_H - r0);
    float* o = out + bc * (OUT_H * OUT_W);

    for (int i = tid; i < out_rows * OUT_W; i += blockDim.x) {
        const int r = i / OUT_W;
        const int c = i - r * OUT_W;
        const float* s0 = &sc[(r    ) * SMEM_W + c];
        const float* s1 = &sc[(r + 1) * SMEM_W + c];
        const float* s2 = &sc[(r + 2) * SMEM_W + c];
        float p = s0[0] * s0[1] * s0[2]
                * s1[0] * s1[1] * s1[2]
                * s2[0] * s2[1] * s2[2];
        o[(r0 + r) * OUT_W + c] = p * cT;
    }
}

extern "C" void kernel_launch(void* const* d_in, const int* in_sizes, int n_in,
                              void* d_out, int out_size)
{
    const float* x     = (const float*)d_in[0];   // [16,3,64,64] float32
    const float* theta = (const float*)d_in[1];   // [10] float32
    float* out = (float*)d_out;                   // [16,3,62,62] float32

    dim3 grid(48, (OUT_H + TILE_H - 1) / TILE_H); // 48 x 4 = 192 blocks
    qconv3x3_coscos_kernel<<<grid, 256>>>(x, theta, out);
}